// round 2
// baseline (speedup 1.0000x reference)
#include <cuda_runtime.h>

// ---------------------------------------------------------------------------
// Problem constants
// ---------------------------------------------------------------------------
#define T0 4096
#define T1 8192
#define BATCH 8
#define KSZ 15
#define PADSZ 7
#define NJ 27

// Scratch (device globals; allocation is forbidden)
__device__ float g_bufA[BATCH * 270 * T1];
__device__ float g_bufB[BATCH * 270 * T1];
__device__ float g_gi[BATCH * 162 * T1];

// ---------------------------------------------------------------------------
// Skeleton adjacency (output joint -> input joints)
// ---------------------------------------------------------------------------
__constant__ int c_nb_cnt[NJ] = {
    8, 7, 6, 5, 4, 7, 6, 5, 4, 7, 8, 9, 6, 3, 7, 5, 4, 3, 7, 5, 4, 3, 6, 5, 6, 5, 12
};
__constant__ int c_nb[NJ][12] = {
    {0, 1, 2, 5, 6, 9, 10, 26, 0, 0, 0, 0},
    {0, 1, 2, 3, 5, 9, 26, 0, 0, 0, 0, 0},
    {0, 1, 2, 3, 4, 26, 0, 0, 0, 0, 0, 0},
    {1, 2, 3, 4, 22, 0, 0, 0, 0, 0, 0, 0},
    {2, 3, 4, 23, 0, 0, 0, 0, 0, 0, 0, 0},
    {0, 1, 5, 6, 7, 9, 26, 0, 0, 0, 0, 0},
    {0, 5, 6, 7, 8, 26, 0, 0, 0, 0, 0, 0},
    {5, 6, 7, 8, 24, 0, 0, 0, 0, 0, 0, 0},
    {6, 7, 8, 25, 0, 0, 0, 0, 0, 0, 0, 0},
    {0, 1, 5, 9, 10, 11, 26, 0, 0, 0, 0, 0},
    {0, 9, 10, 11, 12, 14, 18, 26, 0, 0, 0, 0},
    {9, 10, 11, 12, 13, 14, 15, 18, 19, 0, 0, 0},
    {10, 11, 12, 13, 14, 18, 0, 0, 0, 0, 0, 0},
    {11, 12, 13, 0, 0, 0, 0, 0, 0, 0, 0, 0},
    {10, 11, 12, 14, 15, 16, 18, 0, 0, 0, 0, 0},
    {11, 14, 15, 16, 17, 0, 0, 0, 0, 0, 0, 0},
    {14, 15, 16, 17, 0, 0, 0, 0, 0, 0, 0, 0},
    {15, 16, 17, 0, 0, 0, 0, 0, 0, 0, 0, 0},
    {10, 11, 12, 14, 18, 19, 20, 0, 0, 0, 0, 0},
    {11, 18, 19, 20, 21, 0, 0, 0, 0, 0, 0, 0},
    {18, 19, 20, 21, 0, 0, 0, 0, 0, 0, 0, 0},
    {19, 20, 21, 0, 0, 0, 0, 0, 0, 0, 0, 0},
    {1, 2, 3, 4, 22, 26, 0, 0, 0, 0, 0, 0},
    {2, 3, 4, 23, 26, 0, 0, 0, 0, 0, 0, 0},
    {5, 6, 7, 8, 24, 26, 0, 0, 0, 0, 0, 0},
    {6, 7, 8, 25, 26, 0, 0, 0, 0, 0, 0, 0},
    {0, 1, 2, 5, 6, 9, 10, 22, 23, 24, 25, 26}
};

// Packed dual-FP32 FMA (Blackwell FFMA2). ptxas never emits this from C++.
__device__ __forceinline__ unsigned long long ffma2(unsigned long long a,
                                                    unsigned long long b,
                                                    unsigned long long c)
{
    unsigned long long d;
    asm("fma.rn.f32x2 %0, %1, %2, %3;" : "=l"(d) : "l"(a), "l"(b), "l"(c));
    return d;
}

// ---------------------------------------------------------------------------
// Packed skeleton conv kernel.
//   grid  = (T/512, 27, BATCH), block = (32, NPAIR)
//   Each thread: 16 timesteps x 2 output channels (one f32x2 lane-pair).
//   x staged duplicated {v,v} with 16B pad per 16 pairs -> affine, conflict-free
//   LDS.128. Weights staged channel-pair interleaved {w_co0[k], w_co1[k]}.
// ---------------------------------------------------------------------------
template <int CI_PJ, int CO_PJ, bool ADD_IN, bool ADD_RES, bool LRELU>
__global__ void sconv2_kernel(const float* __restrict__ x,
                              const float* __restrict__ x2,   // added if ADD_IN
                              const float* __restrict__ w,
                              const float* __restrict__ bias,
                              const float* __restrict__ res,  // added if ADD_RES
                              float* __restrict__ y,
                              int T)
{
    constexpr int CIN   = CI_PJ * NJ;
    constexpr int COUT  = CO_PJ * NJ;
    constexpr int NPAIR = (CO_PJ + 1) / 2;
    constexpr int NT    = 32 * NPAIR;
    constexpr int TT    = 512;
    constexpr int TPT   = 16;
    constexpr int NPX   = TT + 2 * PADSZ;   // 526 logical pairs per ci row
    constexpr int XROWB = 4736;             // physical bytes per ci row (16B pad / 16 pairs)
    constexpr int WROWF = 32;               // floats per (pair, ci) weight row

    extern __shared__ char smem[];
    float* swf = (float*)(smem + CI_PJ * XROWB);

    const int b   = blockIdx.z;
    const int j   = blockIdx.y;
    const int t0  = blockIdx.x * TT;
    const int tx  = threadIdx.x;
    const int pr  = threadIdx.y;            // output-channel pair within joint
    const int tid = pr * 32 + tx;

    unsigned long long acc[TPT];
#pragma unroll
    for (int i = 0; i < TPT; ++i) acc[i] = 0ULL;

    const int cnt = c_nb_cnt[j];
    for (int ji = 0; ji < cnt; ++ji) {
        const int jn = c_nb[j][ji];
        __syncthreads();   // protect previous iteration's smem reads

        // ---- stage x tile (duplicated pairs, reflect padding) ----
        {
            const float* xb_  = x + ((size_t)b * CIN + jn * CI_PJ) * (size_t)T;
            const float* x2b_ = ADD_IN
                ? x2 + ((size_t)b * CIN + jn * CI_PJ) * (size_t)T : nullptr;
            for (int idx = tid; idx < CI_PJ * NPX; idx += NT) {
                int ci = idx / NPX;
                int p  = idx - ci * NPX;
                int g  = t0 - PADSZ + p;
                g = (g < 0) ? -g : (g >= T ? 2 * T - 2 - g : g);
                float v = __ldg(xb_ + ci * T + g);
                if (ADD_IN) v += __ldg(x2b_ + ci * T + g);
                *(float2*)(smem + ci * XROWB + 8 * p + 16 * (p >> 4)) =
                    make_float2(v, v);
            }
        }

        // ---- stage weights, channel-pair interleaved ----
        {
            const float* wb_ = w + ((size_t)(j * CO_PJ) * CIN + jn * CI_PJ) * KSZ;
            for (int idx = tid; idx < NPAIR * CI_PJ * WROWF; idx += NT) {
                int slot = idx & 31;
                int row  = idx >> 5;
                int p    = row / CI_PJ;
                int ci   = row - p * CI_PJ;
                int k    = slot >> 1;
                int h    = slot & 1;
                int co   = 2 * p + h;
                float v  = 0.0f;
                if (k < KSZ && co < CO_PJ)
                    v = wb_[((size_t)co * CIN + ci) * KSZ + k];
                swf[idx] = v;
            }
        }
        __syncthreads();

        // ---- accumulate ----
        const char* xptr = smem + 144 * tx;              // +ci*XROWB per ci
        const char* wptr = (const char*)(swf + pr * CI_PJ * WROWF);
#pragma unroll
        for (int ci = 0; ci < CI_PJ; ++ci) {
            unsigned long long xb[2 * TPT - 2];          // 30 duplicated pairs
#pragma unroll
            for (int c = 0; c < 15; ++c) {
                ulonglong2 v = *(const ulonglong2*)(xptr + 16 * c + 16 * (c >> 3));
                xb[2 * c]     = v.x;
                xb[2 * c + 1] = v.y;
            }
#pragma unroll
            for (int kc = 0; kc < 4; ++kc) {             // k chunks of 4
                ulonglong2 w0 = *(const ulonglong2*)(wptr + 32 * kc);
                ulonglong2 w1 = *(const ulonglong2*)(wptr + 32 * kc + 16);
                unsigned long long wp[4] = {w0.x, w0.y, w1.x, w1.y};
#pragma unroll
                for (int kk = 0; kk < 4; ++kk) {
                    constexpr int dummy = 0; (void)dummy;
                    int k = kc * 4 + kk;
                    if (kc * 4 + kk < KSZ) {
#pragma unroll
                        for (int tt = 0; tt < TPT; ++tt)
                            acc[tt] = ffma2(wp[kk], xb[tt + k], acc[tt]);
                    }
                }
            }
            xptr += XROWB;
            wptr += WROWF * 4;  // 128 bytes
        }
    }

    // ---- epilogue: unpack, bias, LeakyReLU, residual, store ----
    const int co0 = j * CO_PJ + 2 * pr;
    const bool has1 = (2 * pr + 1) < CO_PJ;
    const float bv0 = bias[co0];
    const float bv1 = has1 ? bias[co0 + 1] : 0.0f;

    float o0[TPT], o1[TPT];
#pragma unroll
    for (int tt = 0; tt < TPT; ++tt) {
        float lo = __uint_as_float((unsigned)(acc[tt] & 0xffffffffULL));
        float hi = __uint_as_float((unsigned)(acc[tt] >> 32));
        lo += bv0;  hi += bv1;
        if (LRELU) {
            lo = (lo > 0.0f) ? lo : 0.2f * lo;
            hi = (hi > 0.0f) ? hi : 0.2f * hi;
        }
        o0[tt] = lo;  o1[tt] = hi;
    }

    const size_t base0 = ((size_t)b * COUT + co0) * (size_t)T + t0 + 16 * tx;
    if (ADD_RES) {
#pragma unroll
        for (int q = 0; q < 4; ++q) {
            float4 r = *(const float4*)(res + base0 + 4 * q);
            o0[4 * q + 0] += r.x; o0[4 * q + 1] += r.y;
            o0[4 * q + 2] += r.z; o0[4 * q + 3] += r.w;
        }
        if (has1) {
#pragma unroll
            for (int q = 0; q < 4; ++q) {
                float4 r = *(const float4*)(res + base0 + (size_t)T + 4 * q);
                o1[4 * q + 0] += r.x; o1[4 * q + 1] += r.y;
                o1[4 * q + 2] += r.z; o1[4 * q + 3] += r.w;
            }
        }
    }
#pragma unroll
    for (int q = 0; q < 4; ++q)
        *(float4*)(y + base0 + 4 * q) =
            make_float4(o0[4 * q], o0[4 * q + 1], o0[4 * q + 2], o0[4 * q + 3]);
    if (has1) {
#pragma unroll
        for (int q = 0; q < 4; ++q)
            *(float4*)(y + base0 + (size_t)T + 4 * q) =
                make_float4(o1[4 * q], o1[4 * q + 1], o1[4 * q + 2], o1[4 * q + 3]);
    }
}

// ---------------------------------------------------------------------------
// Linear interpolation (align_corners=False)
// ---------------------------------------------------------------------------
__global__ void interp_kernel(const float* __restrict__ in, float* __restrict__ out,
                              int Tin, int Tout, int BC)
{
    int idx = blockIdx.x * blockDim.x + threadIdx.x;
    if (idx >= BC * Tout) return;
    int t  = idx % Tout;
    int bc = idx / Tout;
    float src = ((float)t + 0.5f) * ((float)Tin / (float)Tout) - 0.5f;
    src = fminf(fmaxf(src, 0.0f), (float)(Tin - 1));
    int i0 = (int)floorf(src);
    int i1 = min(i0 + 1, Tin - 1);
    float wgt = src - (float)i0;
    const float* row = in + (size_t)bc * Tin;
    out[idx] = row[i0] * (1.0f - wgt) + row[i1] * wgt;
}

// ---------------------------------------------------------------------------
// Launch
// ---------------------------------------------------------------------------
static inline size_t smem_bytes(int ci_pj, int npair) {
    return (size_t)ci_pj * 4736 + (size_t)npair * ci_pj * 32 * 4;
}

extern "C" void kernel_launch(void* const* d_in, const int* in_sizes, int n_in,
                              void* d_out, int out_size)
{
    (void)in_sizes; (void)n_in; (void)out_size;

    const float* noise0    = (const float*)d_in[0];
    const float* generated = (const float*)d_in[1];
    const float* noise1    = (const float*)d_in[2];

    const float* W[2][4];
    const float* Bv[2][4];
    int idx = 3;
    for (int s = 0; s < 2; ++s)
        for (int l = 0; l < 4; ++l) {
            W[s][l]  = (const float*)d_in[idx++];
            Bv[s][l] = (const float*)d_in[idx++];
        }

    float *bufA, *bufB, *gi;
    cudaGetSymbolAddress((void**)&bufA, g_bufA);
    cudaGetSymbolAddress((void**)&bufB, g_bufB);
    cudaGetSymbolAddress((void**)&gi, g_gi);

    float* g0 = (float*)d_out;
    float* g1 = g0 + (size_t)BATCH * 162 * T0;

    const size_t sm0 = smem_bytes(6, 3);    // L0: 6->5
    const size_t sm1 = smem_bytes(5, 5);    // L1: 5->10
    const size_t sm2 = smem_bytes(10, 5);   // L2: 10->10
    const size_t sm3 = smem_bytes(10, 3);   // L3: 10->6

    cudaFuncSetAttribute(sconv2_kernel<6, 5, true, false, true>,
                         cudaFuncAttributeMaxDynamicSharedMemorySize, (int)sm0);
    cudaFuncSetAttribute(sconv2_kernel<5, 10, false, false, true>,
                         cudaFuncAttributeMaxDynamicSharedMemorySize, (int)sm1);
    cudaFuncSetAttribute(sconv2_kernel<10, 10, false, false, true>,
                         cudaFuncAttributeMaxDynamicSharedMemorySize, (int)sm2);
    cudaFuncSetAttribute(sconv2_kernel<10, 6, false, true, false>,
                         cudaFuncAttributeMaxDynamicSharedMemorySize, (int)sm3);

    // ---------------- stage 0 (T = 4096) ----------------
    {
        dim3 grid(T0 / 512, NJ, BATCH);
        sconv2_kernel<6, 5, true, false, true><<<grid, dim3(32, 3), sm0>>>(
            generated, noise0, W[0][0], Bv[0][0], nullptr, bufA, T0);
        sconv2_kernel<5, 10, false, false, true><<<grid, dim3(32, 5), sm1>>>(
            bufA, nullptr, W[0][1], Bv[0][1], nullptr, bufB, T0);
        sconv2_kernel<10, 10, false, false, true><<<grid, dim3(32, 5), sm2>>>(
            bufB, nullptr, W[0][2], Bv[0][2], nullptr, bufA, T0);
        sconv2_kernel<10, 6, false, true, false><<<grid, dim3(32, 3), sm3>>>(
            bufA, nullptr, W[0][3], Bv[0][3], generated, g0, T0);
    }

    // ---------------- upsample g0 -> gi ----------------
    {
        int n = BATCH * 162 * T1;
        interp_kernel<<<(n + 255) / 256, 256>>>(g0, gi, T0, T1, BATCH * 162);
    }

    // ---------------- stage 1 (T = 8192) ----------------
    {
        dim3 grid(T1 / 512, NJ, BATCH);
        sconv2_kernel<6, 5, true, false, true><<<grid, dim3(32, 3), sm0>>>(
            gi, noise1, W[1][0], Bv[1][0], nullptr, bufA, T1);
        sconv2_kernel<5, 10, false, false, true><<<grid, dim3(32, 5), sm1>>>(
            bufA, nullptr, W[1][1], Bv[1][1], nullptr, bufB, T1);
        sconv2_kernel<10, 10, false, false, true><<<grid, dim3(32, 5), sm2>>>(
            bufB, nullptr, W[1][2], Bv[1][2], nullptr, bufA, T1);
        sconv2_kernel<10, 6, false, true, false><<<grid, dim3(32, 3), sm3>>>(
            bufA, nullptr, W[1][3], Bv[1][3], gi, g1, T1);
    }
}